// round 2
// baseline (speedup 1.0000x reference)
#include <cuda_runtime.h>
#include <cstdint>

// Depthwise 3x3 conv, stride 1, VALID, C=64.
// x: (16, 64, 512, 512) f32, w: (64, 3, 3) f32 -> out: (16, 64, 510, 510) f32
//
// Memory-roofline kernel (floor ~2.13 GB @ ~7 TB/s). No shared memory.
// Each thread owns 4 output columns, rolls a 3-row register window down a
// TILE_H=30 row tile (halo factor 32/30 = 1.067). Math is packed
// fma.rn.f32x2 (FFMA2). Output stores use st.global.cs (write-once data,
// evict-first) to keep L2 for the input halo sharing between row tiles.

#define TILE_H 30   // 510 = 17 * 30
#define THREADS 128 // 128 threads * 4 cols = 512 >= 510

typedef unsigned long long u64;

__device__ __forceinline__ u64 fpack2(float lo, float hi) {
    u64 d;
    asm("mov.b64 %0, {%1, %2};" : "=l"(d) : "f"(lo), "f"(hi));
    return d;
}

__device__ __forceinline__ u64 fmul2(u64 a, u64 b) {
    u64 d;
    asm("mul.rn.f32x2 %0, %1, %2;" : "=l"(d) : "l"(a), "l"(b));
    return d;
}

__device__ __forceinline__ u64 ffma2(u64 a, u64 b, u64 c) {
    u64 d;
    asm("fma.rn.f32x2 %0, %1, %2, %3;" : "=l"(d) : "l"(a), "l"(b), "l"(c));
    return d;
}

__device__ __forceinline__ void stcs64(float* p, u64 v) {
    asm volatile("st.global.cs.u64 [%0], %1;" :: "l"(p), "l"(v) : "memory");
}

// Load 6 consecutive floats at p (16B aligned) -> 5 overlapping f32x2 pairs.
// `last` thread (cols 508..511): cols 512/513 can be OOB at image end; zero
// them (they only feed the two invalid outputs).
__device__ __forceinline__ void load_row_pairs(const float* __restrict__ p,
                                               bool last, u64 q[5]) {
    float4 a = *reinterpret_cast<const float4*>(p);
    float v4 = 0.0f, v5 = 0.0f;
    if (!last) {
        float2 b = *reinterpret_cast<const float2*>(p + 4);
        v4 = b.x;
        v5 = b.y;
    }
    q[0] = fpack2(a.x, a.y);
    q[1] = fpack2(a.y, a.z);
    q[2] = fpack2(a.z, a.w);
    q[3] = fpack2(a.w, v4);
    q[4] = fpack2(v4, v5);
}

__global__ void __launch_bounds__(THREADS)
dwconv3x3_kernel(const float* __restrict__ x,
                 const float* __restrict__ w,
                 float* __restrict__ out) {
    const int tile = blockIdx.x;   // 0..16
    const int c    = blockIdx.y;   // 0..63
    const int n    = blockIdx.z;   // 0..15

    const int tid = threadIdx.x;
    const int x0  = tid * 4;               // first owned output column
    const bool last = (x0 == 508);         // thread 127: 2 valid outputs only

    const size_t img_off = ((size_t)(n * 64 + c)) * (512 * 512);
    const size_t out_off = ((size_t)(n * 64 + c)) * (510 * 510);
    const float* img = x + img_off;
    float* o = out + out_off;

    const int r0 = tile * TILE_H;          // first output row of this tile

    // Broadcast weights as (w,w) f32x2 pairs.
    const float* wc = w + c * 9;
    u64 wp[9];
#pragma unroll
    for (int i = 0; i < 9; ++i) {
        float wv = __ldg(wc + i);
        wp[i] = fpack2(wv, wv);
    }

    // Rolling 3-row window of overlapping pairs.
    u64 q[3][5];
    load_row_pairs(img + (size_t)(r0 + 0) * 512 + x0, last, q[0]);
    load_row_pairs(img + (size_t)(r0 + 1) * 512 + x0, last, q[1]);

    // One step: consume rows (top,mid), load row r0+r+2 into q[bot],
    // emit output row r0+r.
#define STEP(TOP, MID, BOT, R)                                                 \
    {                                                                          \
        const int r = (R);                                                     \
        load_row_pairs(img + (size_t)(r0 + r + 2) * 512 + x0, last, q[BOT]);   \
        u64 acc01 = fmul2(wp[0], q[TOP][0]);                                   \
        acc01 = ffma2(wp[1], q[TOP][1], acc01);                                \
        acc01 = ffma2(wp[2], q[TOP][2], acc01);                                \
        acc01 = ffma2(wp[3], q[MID][0], acc01);                                \
        acc01 = ffma2(wp[4], q[MID][1], acc01);                                \
        acc01 = ffma2(wp[5], q[MID][2], acc01);                                \
        acc01 = ffma2(wp[6], q[BOT][0], acc01);                                \
        acc01 = ffma2(wp[7], q[BOT][1], acc01);                                \
        acc01 = ffma2(wp[8], q[BOT][2], acc01);                                \
        u64 acc23 = fmul2(wp[0], q[TOP][2]);                                   \
        acc23 = ffma2(wp[1], q[TOP][3], acc23);                                \
        acc23 = ffma2(wp[2], q[TOP][4], acc23);                                \
        acc23 = ffma2(wp[3], q[MID][2], acc23);                                \
        acc23 = ffma2(wp[4], q[MID][3], acc23);                                \
        acc23 = ffma2(wp[5], q[MID][4], acc23);                                \
        acc23 = ffma2(wp[6], q[BOT][2], acc23);                                \
        acc23 = ffma2(wp[7], q[BOT][3], acc23);                                \
        acc23 = ffma2(wp[8], q[BOT][4], acc23);                                \
        float* orow = o + (size_t)(r0 + r) * 510 + x0;                         \
        stcs64(orow, acc01);                                                   \
        if (!last) stcs64(orow + 2, acc23);                                    \
    }

#pragma unroll
    for (int rb = 0; rb < TILE_H; rb += 3) {
        STEP(0, 1, 2, rb);
        STEP(1, 2, 0, rb + 1);
        STEP(2, 0, 1, rb + 2);
    }
#undef STEP
}

extern "C" void kernel_launch(void* const* d_in, const int* in_sizes, int n_in,
                              void* d_out, int out_size) {
    const float* x = (const float*)d_in[0];
    const float* w = (const float*)d_in[1];
    // Defensive: metadata order is (x, weight); swap if sizes say otherwise.
    if (n_in >= 2 && in_sizes[0] < in_sizes[1]) {
        const float* t = x; x = w; w = t;
    }
    float* out = (float*)d_out;

    dim3 grid(17, 64, 16); // 510/TILE_H row tiles, C, N
    dwconv3x3_kernel<<<grid, THREADS>>>(x, w, out);
}